// round 3
// baseline (speedup 1.0000x reference)
#include <cuda_runtime.h>
#include <stdint.h>

#define N_NODES 100000
#define N_EDGES 1600000
#define F_IN  64
#define F_HID 64
#define F_OUT 32

// ---------------- static device scratch ----------------
__device__ float g_dinv[N_NODES];
__device__ float g_xws [N_NODES * F_HID];   // (x@W1)*dinv
__device__ float g_h   [N_NODES * F_HID];   // relu hidden
__device__ float g_hws [N_NODES * F_OUT];   // (h@W2)*dinv
__device__ int   g_cnt [N_NODES];
__device__ int   g_off [N_NODES + 1];
__device__ int   g_cur [N_NODES];
__device__ int   g_csr [N_EDGES];
__device__ int   g_is64;

// ---------------- edge index fetch ----------------
__device__ __forceinline__ void get_edge(const int* __restrict__ w, int is64,
                                         int e, int& s, int& d) {
    if (is64) {
        s = w[2 * e];
        d = w[2 * N_EDGES + 2 * e];
    } else {
        s = w[e];
        d = w[N_EDGES + e];
    }
}

__global__ void k_detect(const int* __restrict__ w) {
    int lane = threadIdx.x;
    int nz = (w[2 * lane + 1] != 0) || (w[2 * (lane + 32) + 1] != 0);
    unsigned any = __ballot_sync(0xffffffffu, nz);
    if (lane == 0) g_is64 = (any == 0u);
}

__global__ void k_zero() {
    int i = blockIdx.x * blockDim.x + threadIdx.x;
    if (i < N_NODES) g_cnt[i] = 0;
}

__global__ void k_hist(const int* __restrict__ ew) {
    int e = blockIdx.x * blockDim.x + threadIdx.x;
    if (e >= N_EDGES) return;
    int s, d;
    get_edge(ew, g_is64, e, s, d);
    atomicAdd(&g_cnt[d], 1);
}

__global__ void k_dinv() {
    int i = blockIdx.x * blockDim.x + threadIdx.x;
    if (i >= N_NODES) return;
    g_dinv[i] = rsqrtf((float)g_cnt[i] + 1.0f);
}

__global__ void __launch_bounds__(1024) k_scan() {
    __shared__ int sh[1024];
    const int CH = 98;
    int t = threadIdx.x;
    int base = t * CH;
    int s = 0;
#pragma unroll 7
    for (int i = 0; i < CH; i++) {
        int idx = base + i;
        if (idx < N_NODES) s += g_cnt[idx];
    }
    sh[t] = s;
    __syncthreads();
    for (int ofs = 1; ofs < 1024; ofs <<= 1) {
        int v = (t >= ofs) ? sh[t - ofs] : 0;
        __syncthreads();
        sh[t] += v;
        __syncthreads();
    }
    int run = (t > 0) ? sh[t - 1] : 0;
    for (int i = 0; i < CH; i++) {
        int idx = base + i;
        if (idx < N_NODES) {
            g_off[idx] = run;
            g_cur[idx] = run;
            run += g_cnt[idx];
        }
    }
    if (t == 1023) g_off[N_NODES] = N_EDGES;
}

__global__ void k_fill(const int* __restrict__ ew) {
    int e = blockIdx.x * blockDim.x + threadIdx.x;
    if (e >= N_EDGES) return;
    int s, d;
    get_edge(ew, g_is64, e, s, d);
    int slot = atomicAdd(&g_cur[d], 1);
    g_csr[slot] = s;
}

// ---------------- GEMM1: xws = (x @ W1) * dinv ----------------
__global__ void __launch_bounds__(256) k_gemm1(const float* __restrict__ x,
                                               const float* __restrict__ W) {
    __shared__ float4 ws[F_IN * (F_HID / 4)];
    int tid = threadIdx.x;
    for (int i = tid; i < F_IN * (F_HID / 4); i += 256)
        ws[i] = ((const float4*)W)[i];
    __syncthreads();

    int row = blockIdx.x * 256 + tid;
    if (row >= N_NODES) return;

    float4 acc[16];
#pragma unroll
    for (int j = 0; j < 16; j++) acc[j] = make_float4(0.f, 0.f, 0.f, 0.f);

    const float4* xr = (const float4*)(x + (size_t)row * F_IN);
#pragma unroll
    for (int kk = 0; kk < 16; kk++) {
        float4 xv = __ldg(xr + kk);
        float xs[4] = {xv.x, xv.y, xv.z, xv.w};
#pragma unroll
        for (int t = 0; t < 4; t++) {
            int k = kk * 4 + t;
            float xk = xs[t];
#pragma unroll
            for (int j = 0; j < 16; j++) {
                float4 w4 = ws[k * 16 + j];
                acc[j].x = fmaf(xk, w4.x, acc[j].x);
                acc[j].y = fmaf(xk, w4.y, acc[j].y);
                acc[j].z = fmaf(xk, w4.z, acc[j].z);
                acc[j].w = fmaf(xk, w4.w, acc[j].w);
            }
        }
    }
    float s = g_dinv[row];
    float4* o = (float4*)(g_xws + (size_t)row * F_HID);
#pragma unroll
    for (int j = 0; j < 16; j++) {
        float4 a = acc[j];
        a.x *= s; a.y *= s; a.z *= s; a.w *= s;
        o[j] = a;
    }
}

// ---------------- aggregate layer 1 + hidden epilogue (warp per node) ----------
// pipelined: chunk-of-8 index loads then 8 independent gathers
__global__ void __launch_bounds__(256) k_agg1(const float* __restrict__ b1) {
    int node = (blockIdx.x * 256 + threadIdx.x) >> 5;
    int lane = threadIdx.x & 31;
    if (node >= N_NODES) return;

    int k   = g_off[node];
    int end = g_off[node + 1];

    float2 acc0 = make_float2(0.f, 0.f);
    float2 acc1 = make_float2(0.f, 0.f);
    int col = lane * 2;

    for (; k + 8 <= end; k += 8) {
        int idx[8];
#pragma unroll
        for (int j = 0; j < 8; j++) idx[j] = __ldg(g_csr + k + j);
        float2 v[8];
#pragma unroll
        for (int j = 0; j < 8; j++)
            v[j] = *(const float2*)(g_xws + (size_t)idx[j] * F_HID + col);
#pragma unroll
        for (int j = 0; j < 8; j += 2) {
            acc0.x += v[j].x;     acc0.y += v[j].y;
            acc1.x += v[j + 1].x; acc1.y += v[j + 1].y;
        }
    }
    if (k + 4 <= end) {
        int idx[4];
#pragma unroll
        for (int j = 0; j < 4; j++) idx[j] = __ldg(g_csr + k + j);
        float2 v[4];
#pragma unroll
        for (int j = 0; j < 4; j++)
            v[j] = *(const float2*)(g_xws + (size_t)idx[j] * F_HID + col);
        acc0.x += v[0].x + v[2].x; acc0.y += v[0].y + v[2].y;
        acc1.x += v[1].x + v[3].x; acc1.y += v[1].y + v[3].y;
        k += 4;
    }
    for (; k < end; k++) {
        int s = __ldg(g_csr + k);
        float2 v = *(const float2*)(g_xws + (size_t)s * F_HID + col);
        acc0.x += v.x; acc0.y += v.y;
    }

    float2 self = *(const float2*)(g_xws + (size_t)node * F_HID + col);
    float sc = g_dinv[node];
    float2 b = ((const float2*)b1)[lane];
    float2 r;
    r.x = fmaxf(sc * (acc0.x + acc1.x + self.x) + b.x, 0.f);
    r.y = fmaxf(sc * (acc0.y + acc1.y + self.y) + b.y, 0.f);
    *(float2*)(g_h + (size_t)node * F_HID + col) = r;
}

// ---------------- GEMM2: hws = (h @ W2) * dinv ----------------
__global__ void __launch_bounds__(256) k_gemm2(const float* __restrict__ W) {
    __shared__ float4 ws[F_HID * (F_OUT / 4)];
    int tid = threadIdx.x;
    for (int i = tid; i < F_HID * (F_OUT / 4); i += 256)
        ws[i] = ((const float4*)W)[i];
    __syncthreads();

    int row = blockIdx.x * 256 + tid;
    if (row >= N_NODES) return;

    float4 acc[8];
#pragma unroll
    for (int j = 0; j < 8; j++) acc[j] = make_float4(0.f, 0.f, 0.f, 0.f);

    const float4* hr = (const float4*)(g_h + (size_t)row * F_HID);
#pragma unroll
    for (int kk = 0; kk < 16; kk++) {
        float4 hv = __ldg(hr + kk);
        float hs[4] = {hv.x, hv.y, hv.z, hv.w};
#pragma unroll
        for (int t = 0; t < 4; t++) {
            int k = kk * 4 + t;
            float hk = hs[t];
#pragma unroll
            for (int j = 0; j < 8; j++) {
                float4 w4 = ws[k * 8 + j];
                acc[j].x = fmaf(hk, w4.x, acc[j].x);
                acc[j].y = fmaf(hk, w4.y, acc[j].y);
                acc[j].z = fmaf(hk, w4.z, acc[j].z);
                acc[j].w = fmaf(hk, w4.w, acc[j].w);
            }
        }
    }
    float s = g_dinv[row];
    float4* o = (float4*)(g_hws + (size_t)row * F_OUT);
#pragma unroll
    for (int j = 0; j < 8; j++) {
        float4 a = acc[j];
        a.x *= s; a.y *= s; a.z *= s; a.w *= s;
        o[j] = a;
    }
}

// ---------------- aggregate layer 2 + output epilogue (warp per node) ----------
__global__ void __launch_bounds__(256) k_agg2(const float* __restrict__ b2,
                                              float* __restrict__ out) {
    int node = (blockIdx.x * 256 + threadIdx.x) >> 5;
    int lane = threadIdx.x & 31;
    if (node >= N_NODES) return;

    int k   = g_off[node];
    int end = g_off[node + 1];

    float acc0 = 0.f, acc1 = 0.f;

    for (; k + 8 <= end; k += 8) {
        int idx[8];
#pragma unroll
        for (int j = 0; j < 8; j++) idx[j] = __ldg(g_csr + k + j);
        float v[8];
#pragma unroll
        for (int j = 0; j < 8; j++)
            v[j] = g_hws[(size_t)idx[j] * F_OUT + lane];
        acc0 += (v[0] + v[2]) + (v[4] + v[6]);
        acc1 += (v[1] + v[3]) + (v[5] + v[7]);
    }
    if (k + 4 <= end) {
        int idx[4];
#pragma unroll
        for (int j = 0; j < 4; j++) idx[j] = __ldg(g_csr + k + j);
        float v[4];
#pragma unroll
        for (int j = 0; j < 4; j++)
            v[j] = g_hws[(size_t)idx[j] * F_OUT + lane];
        acc0 += v[0] + v[2];
        acc1 += v[1] + v[3];
        k += 4;
    }
    for (; k < end; k++) {
        int s = __ldg(g_csr + k);
        acc0 += g_hws[(size_t)s * F_OUT + lane];
    }

    float self = g_hws[(size_t)node * F_OUT + lane];
    float sc = g_dinv[node];
    out[(size_t)node * F_OUT + lane] = sc * (acc0 + acc1 + self) + b2[lane];
}

// ---------------- launch ----------------
extern "C" void kernel_launch(void* const* d_in, const int* in_sizes, int n_in,
                              void* d_out, int out_size) {
    const float* x  = (const float*)d_in[0];
    const int*   ew = (const int*)d_in[1];
    const float* W1 = (const float*)d_in[2];
    const float* b1 = (const float*)d_in[3];
    const float* W2 = (const float*)d_in[4];
    const float* b2 = (const float*)d_in[5];
    float* out = (float*)d_out;

    const int T = 256;

    k_detect<<<1, 32>>>(ew);
    k_zero<<<(N_NODES + T - 1) / T, T>>>();
    k_hist<<<(N_EDGES + T - 1) / T, T>>>(ew);
    k_dinv<<<(N_NODES + T - 1) / T, T>>>();
    k_scan<<<1, 1024>>>();
    k_fill<<<(N_EDGES + T - 1) / T, T>>>(ew);

    k_gemm1<<<(N_NODES + T - 1) / T, T>>>(x, W1);
    k_agg1<<<(N_NODES * 32 + T - 1) / T, T>>>(b1);

    k_gemm2<<<(N_NODES + T - 1) / T, T>>>(W2);
    k_agg2<<<(N_NODES * 32 + T - 1) / T, T>>>(b2, out);
}

// round 4
// speedup vs baseline: 1.8354x; 1.8354x over previous
#include <cuda_runtime.h>
#include <stdint.h>

#define N_NODES 100000
#define N_EDGES 1600000
#define F_IN  64
#define F_HID 64
#define F_OUT 32

#define SCAN_B 98   // 98 * 1024 >= N_NODES

// ---------------- static device scratch ----------------
__device__ float g_dinv[N_NODES];
__device__ float g_xws [N_NODES * F_HID];   // (x@W1)*dinv
__device__ float g_h   [N_NODES * F_HID];   // relu hidden
__device__ float g_hws [N_NODES * F_OUT];   // (h@W2)*dinv
__device__ int   g_cnt [N_NODES];
__device__ int   g_off [N_NODES + 1];
__device__ int   g_cur [N_NODES];
__device__ int   g_csr [N_EDGES];
__device__ int   g_bsum[SCAN_B];
__device__ int   g_bbase[SCAN_B];
__device__ int   g_is64;

// ---------------- edge index fetch ----------------
__device__ __forceinline__ void get_edge(const int* __restrict__ w, int is64,
                                         int e, int& s, int& d) {
    if (is64) {
        s = w[2 * e];
        d = w[2 * N_EDGES + 2 * e];
    } else {
        s = w[e];
        d = w[N_EDGES + e];
    }
}

__global__ void k_detect(const int* __restrict__ w) {
    int lane = threadIdx.x;
    int nz = (w[2 * lane + 1] != 0) || (w[2 * (lane + 32) + 1] != 0);
    unsigned any = __ballot_sync(0xffffffffu, nz);
    if (lane == 0) g_is64 = (any == 0u);
}

__global__ void k_zero() {
    int i = blockIdx.x * blockDim.x + threadIdx.x;
    if (i < N_NODES) g_cnt[i] = 0;
}

__global__ void k_hist(const int* __restrict__ ew) {
    int e = blockIdx.x * blockDim.x + threadIdx.x;
    if (e >= N_EDGES) return;
    int s, d;
    get_edge(ew, g_is64, e, s, d);
    atomicAdd(&g_cnt[d], 1);
}

// ---------------- coalesced 3-pass scan ----------------
// pass 1: per-block sums
__global__ void __launch_bounds__(1024) k_scan_red() {
    int i = blockIdx.x * 1024 + threadIdx.x;
    int v = (i < N_NODES) ? g_cnt[i] : 0;
#pragma unroll
    for (int o = 16; o > 0; o >>= 1) v += __shfl_down_sync(0xffffffffu, v, o);
    __shared__ int ws[32];
    int lane = threadIdx.x & 31, wid = threadIdx.x >> 5;
    if (lane == 0) ws[wid] = v;
    __syncthreads();
    if (wid == 0) {
        int s = ws[lane];
#pragma unroll
        for (int o = 16; o > 0; o >>= 1) s += __shfl_down_sync(0xffffffffu, s, o);
        if (lane == 0) g_bsum[blockIdx.x] = s;
    }
}

// pass 2: exclusive scan of SCAN_B block sums (one block of 128)
__global__ void __launch_bounds__(128) k_scan_base() {
    __shared__ int sh[128];
    int t = threadIdx.x;
    int v = (t < SCAN_B) ? g_bsum[t] : 0;
    sh[t] = v;
    __syncthreads();
    for (int o = 1; o < 128; o <<= 1) {
        int u = (t >= o) ? sh[t - o] : 0;
        __syncthreads();
        sh[t] += u;
        __syncthreads();
    }
    if (t < SCAN_B) g_bbase[t] = sh[t] - v;   // exclusive
    if (t == 0) g_off[N_NODES] = N_EDGES;
}

// pass 3: block-local exclusive scan + base, write off/cur, fuse dinv
__global__ void __launch_bounds__(1024) k_scan_write() {
    int t = threadIdx.x;
    int i = blockIdx.x * 1024 + t;
    int lane = t & 31, wid = t >> 5;
    int c = (i < N_NODES) ? g_cnt[i] : 0;

    // warp inclusive scan
    int inc = c;
#pragma unroll
    for (int o = 1; o < 32; o <<= 1) {
        int u = __shfl_up_sync(0xffffffffu, inc, o);
        if (lane >= o) inc += u;
    }
    __shared__ int wpre[32];
    if (lane == 31) wpre[wid] = inc;
    __syncthreads();
    if (wid == 0) {
        int s = wpre[lane];
        int sinc = s;
#pragma unroll
        for (int o = 1; o < 32; o <<= 1) {
            int u = __shfl_up_sync(0xffffffffu, sinc, o);
            if (lane >= o) sinc += u;
        }
        wpre[lane] = sinc - s;   // exclusive warp prefix
    }
    __syncthreads();

    if (i < N_NODES) {
        int exc = inc - c + wpre[wid] + g_bbase[blockIdx.x];
        g_off[i] = exc;
        g_cur[i] = exc;
        g_dinv[i] = rsqrtf((float)c + 1.0f);
    }
}

__global__ void k_fill(const int* __restrict__ ew) {
    int e = blockIdx.x * blockDim.x + threadIdx.x;
    if (e >= N_EDGES) return;
    int s, d;
    get_edge(ew, g_is64, e, s, d);
    int slot = atomicAdd(&g_cur[d], 1);
    g_csr[slot] = s;
}

// ---------------- GEMM1: xws = (x @ W1) * dinv ----------------
__global__ void __launch_bounds__(256) k_gemm1(const float* __restrict__ x,
                                               const float* __restrict__ W) {
    __shared__ float4 ws[F_IN * (F_HID / 4)];
    int tid = threadIdx.x;
    for (int i = tid; i < F_IN * (F_HID / 4); i += 256)
        ws[i] = ((const float4*)W)[i];
    __syncthreads();

    int row = blockIdx.x * 256 + tid;
    if (row >= N_NODES) return;

    float4 acc[16];
#pragma unroll
    for (int j = 0; j < 16; j++) acc[j] = make_float4(0.f, 0.f, 0.f, 0.f);

    const float4* xr = (const float4*)(x + (size_t)row * F_IN);
#pragma unroll
    for (int kk = 0; kk < 16; kk++) {
        float4 xv = __ldg(xr + kk);
        float xs[4] = {xv.x, xv.y, xv.z, xv.w};
#pragma unroll
        for (int t = 0; t < 4; t++) {
            int k = kk * 4 + t;
            float xk = xs[t];
#pragma unroll
            for (int j = 0; j < 16; j++) {
                float4 w4 = ws[k * 16 + j];
                acc[j].x = fmaf(xk, w4.x, acc[j].x);
                acc[j].y = fmaf(xk, w4.y, acc[j].y);
                acc[j].z = fmaf(xk, w4.z, acc[j].z);
                acc[j].w = fmaf(xk, w4.w, acc[j].w);
            }
        }
    }
    float s = g_dinv[row];
    float4* o = (float4*)(g_xws + (size_t)row * F_HID);
#pragma unroll
    for (int j = 0; j < 16; j++) {
        float4 a = acc[j];
        a.x *= s; a.y *= s; a.z *= s; a.w *= s;
        o[j] = a;
    }
}

// ---------------- aggregate layer 1 + hidden epilogue (warp per node) ----------
__global__ void __launch_bounds__(256) k_agg1(const float* __restrict__ b1) {
    int node = (blockIdx.x * 256 + threadIdx.x) >> 5;
    int lane = threadIdx.x & 31;
    if (node >= N_NODES) return;

    int k   = g_off[node];
    int end = g_off[node + 1];

    float2 acc0 = make_float2(0.f, 0.f);
    float2 acc1 = make_float2(0.f, 0.f);
    int col = lane * 2;

    for (; k + 8 <= end; k += 8) {
        int idx[8];
#pragma unroll
        for (int j = 0; j < 8; j++) idx[j] = __ldg(g_csr + k + j);
        float2 v[8];
#pragma unroll
        for (int j = 0; j < 8; j++)
            v[j] = *(const float2*)(g_xws + (size_t)idx[j] * F_HID + col);
#pragma unroll
        for (int j = 0; j < 8; j += 2) {
            acc0.x += v[j].x;     acc0.y += v[j].y;
            acc1.x += v[j + 1].x; acc1.y += v[j + 1].y;
        }
    }
    if (k + 4 <= end) {
        int idx[4];
#pragma unroll
        for (int j = 0; j < 4; j++) idx[j] = __ldg(g_csr + k + j);
        float2 v[4];
#pragma unroll
        for (int j = 0; j < 4; j++)
            v[j] = *(const float2*)(g_xws + (size_t)idx[j] * F_HID + col);
        acc0.x += v[0].x + v[2].x; acc0.y += v[0].y + v[2].y;
        acc1.x += v[1].x + v[3].x; acc1.y += v[1].y + v[3].y;
        k += 4;
    }
    for (; k < end; k++) {
        int s = __ldg(g_csr + k);
        float2 v = *(const float2*)(g_xws + (size_t)s * F_HID + col);
        acc0.x += v.x; acc0.y += v.y;
    }

    float2 self = *(const float2*)(g_xws + (size_t)node * F_HID + col);
    float sc = g_dinv[node];
    float2 b = ((const float2*)b1)[lane];
    float2 r;
    r.x = fmaxf(sc * (acc0.x + acc1.x + self.x) + b.x, 0.f);
    r.y = fmaxf(sc * (acc0.y + acc1.y + self.y) + b.y, 0.f);
    *(float2*)(g_h + (size_t)node * F_HID + col) = r;
}

// ---------------- GEMM2: hws = (h @ W2) * dinv ----------------
__global__ void __launch_bounds__(256) k_gemm2(const float* __restrict__ W) {
    __shared__ float4 ws[F_HID * (F_OUT / 4)];
    int tid = threadIdx.x;
    for (int i = tid; i < F_HID * (F_OUT / 4); i += 256)
        ws[i] = ((const float4*)W)[i];
    __syncthreads();

    int row = blockIdx.x * 256 + tid;
    if (row >= N_NODES) return;

    float4 acc[8];
#pragma unroll
    for (int j = 0; j < 8; j++) acc[j] = make_float4(0.f, 0.f, 0.f, 0.f);

    const float4* hr = (const float4*)(g_h + (size_t)row * F_HID);
#pragma unroll
    for (int kk = 0; kk < 16; kk++) {
        float4 hv = __ldg(hr + kk);
        float hs[4] = {hv.x, hv.y, hv.z, hv.w};
#pragma unroll
        for (int t = 0; t < 4; t++) {
            int k = kk * 4 + t;
            float hk = hs[t];
#pragma unroll
            for (int j = 0; j < 8; j++) {
                float4 w4 = ws[k * 8 + j];
                acc[j].x = fmaf(hk, w4.x, acc[j].x);
                acc[j].y = fmaf(hk, w4.y, acc[j].y);
                acc[j].z = fmaf(hk, w4.z, acc[j].z);
                acc[j].w = fmaf(hk, w4.w, acc[j].w);
            }
        }
    }
    float s = g_dinv[row];
    float4* o = (float4*)(g_hws + (size_t)row * F_OUT);
#pragma unroll
    for (int j = 0; j < 8; j++) {
        float4 a = acc[j];
        a.x *= s; a.y *= s; a.z *= s; a.w *= s;
        o[j] = a;
    }
}

// ---------------- aggregate layer 2 + output epilogue (warp per node) ----------
__global__ void __launch_bounds__(256) k_agg2(const float* __restrict__ b2,
                                              float* __restrict__ out) {
    int node = (blockIdx.x * 256 + threadIdx.x) >> 5;
    int lane = threadIdx.x & 31;
    if (node >= N_NODES) return;

    int k   = g_off[node];
    int end = g_off[node + 1];

    float acc0 = 0.f, acc1 = 0.f;

    for (; k + 8 <= end; k += 8) {
        int idx[8];
#pragma unroll
        for (int j = 0; j < 8; j++) idx[j] = __ldg(g_csr + k + j);
        float v[8];
#pragma unroll
        for (int j = 0; j < 8; j++)
            v[j] = g_hws[(size_t)idx[j] * F_OUT + lane];
        acc0 += (v[0] + v[2]) + (v[4] + v[6]);
        acc1 += (v[1] + v[3]) + (v[5] + v[7]);
    }
    if (k + 4 <= end) {
        int idx[4];
#pragma unroll
        for (int j = 0; j < 4; j++) idx[j] = __ldg(g_csr + k + j);
        float v[4];
#pragma unroll
        for (int j = 0; j < 4; j++)
            v[j] = g_hws[(size_t)idx[j] * F_OUT + lane];
        acc0 += v[0] + v[2];
        acc1 += v[1] + v[3];
        k += 4;
    }
    for (; k < end; k++) {
        int s = __ldg(g_csr + k);
        acc0 += g_hws[(size_t)s * F_OUT + lane];
    }

    float self = g_hws[(size_t)node * F_OUT + lane];
    float sc = g_dinv[node];
    out[(size_t)node * F_OUT + lane] = sc * (acc0 + acc1 + self) + b2[lane];
}

// ---------------- launch ----------------
extern "C" void kernel_launch(void* const* d_in, const int* in_sizes, int n_in,
                              void* d_out, int out_size) {
    const float* x  = (const float*)d_in[0];
    const int*   ew = (const int*)d_in[1];
    const float* W1 = (const float*)d_in[2];
    const float* b1 = (const float*)d_in[3];
    const float* W2 = (const float*)d_in[4];
    const float* b2 = (const float*)d_in[5];
    float* out = (float*)d_out;

    const int T = 256;

    k_detect<<<1, 32>>>(ew);
    k_zero<<<(N_NODES + T - 1) / T, T>>>();
    k_hist<<<(N_EDGES + T - 1) / T, T>>>(ew);
    k_scan_red<<<SCAN_B, 1024>>>();
    k_scan_base<<<1, 128>>>();
    k_scan_write<<<SCAN_B, 1024>>>();
    k_fill<<<(N_EDGES + T - 1) / T, T>>>(ew);

    k_gemm1<<<(N_NODES + T - 1) / T, T>>>(x, W1);
    k_agg1<<<(N_NODES * 32 + T - 1) / T, T>>>(b1);

    k_gemm2<<<(N_NODES + T - 1) / T, T>>>(W2);
    k_agg2<<<(N_NODES * 32 + T - 1) / T, T>>>(b2, out);
}

// round 5
// speedup vs baseline: 2.0193x; 1.1002x over previous
#include <cuda_runtime.h>
#include <cuda_fp16.h>
#include <stdint.h>

#define N_NODES 100000
#define N_EDGES 1600000
#define F_IN  64
#define F_HID 64
#define F_OUT 32

#define SCAN_B 98   // 98 * 1024 >= N_NODES

// ---------------- static device scratch ----------------
__device__ float  g_dinv[N_NODES];
__device__ __half g_xws [N_NODES * F_HID];   // (x@W1)*dinv, fp16
__device__ float  g_h   [N_NODES * F_HID];   // relu hidden (fp32, gemm2 input)
__device__ __half g_hws [N_NODES * F_OUT];   // (h@W2)*dinv, fp16
__device__ int    g_cnt [N_NODES];
__device__ int    g_off [N_NODES + 1];
__device__ int    g_cur [N_NODES];
__device__ int    g_csr [N_EDGES];
__device__ int    g_bsum[SCAN_B];
__device__ int    g_bbase[SCAN_B];
__device__ int    g_is64;

// ---------------- edge index fetch ----------------
__device__ __forceinline__ void get_edge(const int* __restrict__ w, int is64,
                                         int e, int& s, int& d) {
    if (is64) {
        s = w[2 * e];
        d = w[2 * N_EDGES + 2 * e];
    } else {
        s = w[e];
        d = w[N_EDGES + e];
    }
}

__global__ void k_detect(const int* __restrict__ w) {
    int lane = threadIdx.x;
    int nz = (w[2 * lane + 1] != 0) || (w[2 * (lane + 32) + 1] != 0);
    unsigned any = __ballot_sync(0xffffffffu, nz);
    if (lane == 0) g_is64 = (any == 0u);
}

__global__ void k_zero() {
    int i = blockIdx.x * blockDim.x + threadIdx.x;
    if (i < N_NODES) g_cnt[i] = 0;
}

__global__ void k_hist(const int* __restrict__ ew) {
    int e = blockIdx.x * blockDim.x + threadIdx.x;
    if (e >= N_EDGES) return;
    int s, d;
    get_edge(ew, g_is64, e, s, d);
    atomicAdd(&g_cnt[d], 1);
}

// ---------------- coalesced 3-pass scan ----------------
__global__ void __launch_bounds__(1024) k_scan_red() {
    int i = blockIdx.x * 1024 + threadIdx.x;
    int v = (i < N_NODES) ? g_cnt[i] : 0;
#pragma unroll
    for (int o = 16; o > 0; o >>= 1) v += __shfl_down_sync(0xffffffffu, v, o);
    __shared__ int ws[32];
    int lane = threadIdx.x & 31, wid = threadIdx.x >> 5;
    if (lane == 0) ws[wid] = v;
    __syncthreads();
    if (wid == 0) {
        int s = ws[lane];
#pragma unroll
        for (int o = 16; o > 0; o >>= 1) s += __shfl_down_sync(0xffffffffu, s, o);
        if (lane == 0) g_bsum[blockIdx.x] = s;
    }
}

__global__ void __launch_bounds__(128) k_scan_base() {
    __shared__ int sh[128];
    int t = threadIdx.x;
    int v = (t < SCAN_B) ? g_bsum[t] : 0;
    sh[t] = v;
    __syncthreads();
    for (int o = 1; o < 128; o <<= 1) {
        int u = (t >= o) ? sh[t - o] : 0;
        __syncthreads();
        sh[t] += u;
        __syncthreads();
    }
    if (t < SCAN_B) g_bbase[t] = sh[t] - v;
    if (t == 0) g_off[N_NODES] = N_EDGES;
}

__global__ void __launch_bounds__(1024) k_scan_write() {
    int t = threadIdx.x;
    int i = blockIdx.x * 1024 + t;
    int lane = t & 31, wid = t >> 5;
    int c = (i < N_NODES) ? g_cnt[i] : 0;

    int inc = c;
#pragma unroll
    for (int o = 1; o < 32; o <<= 1) {
        int u = __shfl_up_sync(0xffffffffu, inc, o);
        if (lane >= o) inc += u;
    }
    __shared__ int wpre[32];
    if (lane == 31) wpre[wid] = inc;
    __syncthreads();
    if (wid == 0) {
        int s = wpre[lane];
        int sinc = s;
#pragma unroll
        for (int o = 1; o < 32; o <<= 1) {
            int u = __shfl_up_sync(0xffffffffu, sinc, o);
            if (lane >= o) sinc += u;
        }
        wpre[lane] = sinc - s;
    }
    __syncthreads();

    if (i < N_NODES) {
        int exc = inc - c + wpre[wid] + g_bbase[blockIdx.x];
        g_off[i] = exc;
        g_cur[i] = exc;
        g_dinv[i] = rsqrtf((float)c + 1.0f);
    }
}

__global__ void k_fill(const int* __restrict__ ew) {
    int e = blockIdx.x * blockDim.x + threadIdx.x;
    if (e >= N_EDGES) return;
    int s, d;
    get_edge(ew, g_is64, e, s, d);
    int slot = atomicAdd(&g_cur[d], 1);
    g_csr[slot] = s;
}

// ---------------- GEMM1: xws = fp16((x @ W1) * dinv) ----------------
__global__ void __launch_bounds__(256) k_gemm1(const float* __restrict__ x,
                                               const float* __restrict__ W) {
    __shared__ float4 ws[F_IN * (F_HID / 4)];
    int tid = threadIdx.x;
    for (int i = tid; i < F_IN * (F_HID / 4); i += 256)
        ws[i] = ((const float4*)W)[i];
    __syncthreads();

    int row = blockIdx.x * 256 + tid;
    if (row >= N_NODES) return;

    float4 acc[16];
#pragma unroll
    for (int j = 0; j < 16; j++) acc[j] = make_float4(0.f, 0.f, 0.f, 0.f);

    const float4* xr = (const float4*)(x + (size_t)row * F_IN);
#pragma unroll
    for (int kk = 0; kk < 16; kk++) {
        float4 xv = __ldg(xr + kk);
        float xs[4] = {xv.x, xv.y, xv.z, xv.w};
#pragma unroll
        for (int t = 0; t < 4; t++) {
            int k = kk * 4 + t;
            float xk = xs[t];
#pragma unroll
            for (int j = 0; j < 16; j++) {
                float4 w4 = ws[k * 16 + j];
                acc[j].x = fmaf(xk, w4.x, acc[j].x);
                acc[j].y = fmaf(xk, w4.y, acc[j].y);
                acc[j].z = fmaf(xk, w4.z, acc[j].z);
                acc[j].w = fmaf(xk, w4.w, acc[j].w);
            }
        }
    }
    float s = g_dinv[row];
    __half2 hrow[32];
#pragma unroll
    for (int j = 0; j < 16; j++) {
        hrow[2 * j]     = __floats2half2_rn(acc[j].x * s, acc[j].y * s);
        hrow[2 * j + 1] = __floats2half2_rn(acc[j].z * s, acc[j].w * s);
    }
    uint4* o = (uint4*)(g_xws + (size_t)row * F_HID);
    const uint4* hp = (const uint4*)hrow;
#pragma unroll
    for (int j = 0; j < 8; j++) o[j] = hp[j];
}

// ---------------- aggregate layer 1 + hidden epilogue (warp per node) ----------
__global__ void __launch_bounds__(256) k_agg1(const float* __restrict__ b1) {
    int node = (blockIdx.x * 256 + threadIdx.x) >> 5;
    int lane = threadIdx.x & 31;
    if (node >= N_NODES) return;

    int k   = g_off[node];
    int end = g_off[node + 1];

    float2 acc0 = make_float2(0.f, 0.f);
    float2 acc1 = make_float2(0.f, 0.f);
    int col = lane * 2;

    for (; k + 8 <= end; k += 8) {
        int idx[8];
#pragma unroll
        for (int j = 0; j < 8; j++) idx[j] = __ldg(g_csr + k + j);
        __half2 v[8];
#pragma unroll
        for (int j = 0; j < 8; j++)
            v[j] = *(const __half2*)(g_xws + (size_t)idx[j] * F_HID + col);
#pragma unroll
        for (int j = 0; j < 8; j += 2) {
            float2 f0 = __half22float2(v[j]);
            float2 f1 = __half22float2(v[j + 1]);
            acc0.x += f0.x; acc0.y += f0.y;
            acc1.x += f1.x; acc1.y += f1.y;
        }
    }
    for (; k < end; k++) {
        int s = __ldg(g_csr + k);
        float2 f = __half22float2(*(const __half2*)(g_xws + (size_t)s * F_HID + col));
        acc0.x += f.x; acc0.y += f.y;
    }

    float2 self = __half22float2(*(const __half2*)(g_xws + (size_t)node * F_HID + col));
    float sc = g_dinv[node];
    float2 b = ((const float2*)b1)[lane];
    float2 r;
    r.x = fmaxf(sc * (acc0.x + acc1.x + self.x) + b.x, 0.f);
    r.y = fmaxf(sc * (acc0.y + acc1.y + self.y) + b.y, 0.f);
    *(float2*)(g_h + (size_t)node * F_HID + col) = r;
}

// ---------------- GEMM2: hws = fp16((h @ W2) * dinv) ----------------
__global__ void __launch_bounds__(256) k_gemm2(const float* __restrict__ W) {
    __shared__ float4 ws[F_HID * (F_OUT / 4)];
    int tid = threadIdx.x;
    for (int i = tid; i < F_HID * (F_OUT / 4); i += 256)
        ws[i] = ((const float4*)W)[i];
    __syncthreads();

    int row = blockIdx.x * 256 + tid;
    if (row >= N_NODES) return;

    float4 acc[8];
#pragma unroll
    for (int j = 0; j < 8; j++) acc[j] = make_float4(0.f, 0.f, 0.f, 0.f);

    const float4* hr = (const float4*)(g_h + (size_t)row * F_HID);
#pragma unroll
    for (int kk = 0; kk < 16; kk++) {
        float4 hv = __ldg(hr + kk);
        float hs[4] = {hv.x, hv.y, hv.z, hv.w};
#pragma unroll
        for (int t = 0; t < 4; t++) {
            int k = kk * 4 + t;
            float hk = hs[t];
#pragma unroll
            for (int j = 0; j < 8; j++) {
                float4 w4 = ws[k * 8 + j];
                acc[j].x = fmaf(hk, w4.x, acc[j].x);
                acc[j].y = fmaf(hk, w4.y, acc[j].y);
                acc[j].z = fmaf(hk, w4.z, acc[j].z);
                acc[j].w = fmaf(hk, w4.w, acc[j].w);
            }
        }
    }
    float s = g_dinv[row];
    __half2 hrow[16];
#pragma unroll
    for (int j = 0; j < 8; j++) {
        hrow[2 * j]     = __floats2half2_rn(acc[j].x * s, acc[j].y * s);
        hrow[2 * j + 1] = __floats2half2_rn(acc[j].z * s, acc[j].w * s);
    }
    uint4* o = (uint4*)(g_hws + (size_t)row * F_OUT);
    const uint4* hp = (const uint4*)hrow;
#pragma unroll
    for (int j = 0; j < 4; j++) o[j] = hp[j];
}

// ---------------- aggregate layer 2 + output epilogue (warp per node) ----------
__global__ void __launch_bounds__(256) k_agg2(const float* __restrict__ b2,
                                              float* __restrict__ out) {
    int node = (blockIdx.x * 256 + threadIdx.x) >> 5;
    int lane = threadIdx.x & 31;
    if (node >= N_NODES) return;

    int k   = g_off[node];
    int end = g_off[node + 1];

    float acc0 = 0.f, acc1 = 0.f;

    for (; k + 8 <= end; k += 8) {
        int idx[8];
#pragma unroll
        for (int j = 0; j < 8; j++) idx[j] = __ldg(g_csr + k + j);
        float v[8];
#pragma unroll
        for (int j = 0; j < 8; j++)
            v[j] = __half2float(g_hws[(size_t)idx[j] * F_OUT + lane]);
        acc0 += (v[0] + v[2]) + (v[4] + v[6]);
        acc1 += (v[1] + v[3]) + (v[5] + v[7]);
    }
    for (; k < end; k++) {
        int s = __ldg(g_csr + k);
        acc0 += __half2float(g_hws[(size_t)s * F_OUT + lane]);
    }

    float self = __half2float(g_hws[(size_t)node * F_OUT + lane]);
    float sc = g_dinv[node];
    out[(size_t)node * F_OUT + lane] = sc * (acc0 + acc1 + self) + b2[lane];
}

// ---------------- launch ----------------
extern "C" void kernel_launch(void* const* d_in, const int* in_sizes, int n_in,
                              void* d_out, int out_size) {
    const float* x  = (const float*)d_in[0];
    const int*   ew = (const int*)d_in[1];
    const float* W1 = (const float*)d_in[2];
    const float* b1 = (const float*)d_in[3];
    const float* W2 = (const float*)d_in[4];
    const float* b2 = (const float*)d_in[5];
    float* out = (float*)d_out;

    const int T = 256;

    k_detect<<<1, 32>>>(ew);
    k_zero<<<(N_NODES + T - 1) / T, T>>>();
    k_hist<<<(N_EDGES + T - 1) / T, T>>>(ew);
    k_scan_red<<<SCAN_B, 1024>>>();
    k_scan_base<<<1, 128>>>();
    k_scan_write<<<SCAN_B, 1024>>>();
    k_fill<<<(N_EDGES + T - 1) / T, T>>>(ew);

    k_gemm1<<<(N_NODES + T - 1) / T, T>>>(x, W1);
    k_agg1<<<(N_NODES * 32 + T - 1) / T, T>>>(b1);

    k_gemm2<<<(N_NODES + T - 1) / T, T>>>(W2);
    k_agg2<<<(N_NODES * 32 + T - 1) / T, T>>>(b2, out);
}